// round 15
// baseline (speedup 1.0000x reference)
#include <cuda_runtime.h>
#include <cuda_bf16.h>
#include <math.h>
#include <stdint.h>

// Problem constants (fixed by setup_inputs)
#define BB   4
#define SS   8192
#define HH   16
#define DD   128
#define NB   64      // SS / 128
#define HID  32
#define HID2 16
#define KP   1024    // nb*nb*0.25
#define NGROUPS (BB*HH)   // 64
#define GSIZE   (NB*NB)   // 4096
#define NSTG 3            // TMA pipeline stages
#define CHUNK 16384       // bytes per stage = 2 s-rows

// ---- scratch (device globals; no allocation allowed) ----
__device__ float g_imp [2][BB*NB*HH];      // importance scores
__device__ float g_part[2][BB*NB*HH*HID];  // q_part / k_part
__device__ float g_scores[BB*HH*GSIZE];    // combined, flat-linear order

__device__ __forceinline__ uint32_t smem_u32(const void* p) {
    uint32_t a;
    asm("{ .reg .u64 t; cvta.to.shared.u64 t, %1; cvt.u32.u64 %0, t; }"
        : "=r"(a) : "l"(p));
    return a;
}

__device__ __forceinline__ void mbar_wait(uint32_t mbar, int phase) {
    asm volatile(
        "{\n\t"
        ".reg .pred P;\n\t"
        "W%=:\n\t"
        "mbarrier.try_wait.parity.acquire.cta.shared::cta.b64 P, [%0], %1, 0x989680;\n\t"
        "@P bra D%=;\n\t"
        "bra W%=;\n\t"
        "D%=:\n\t"
        "}"
        :: "r"(mbar), "r"(phase) : "memory");
}

// ============================================================
// K1: fused block-mean pooling + importance MLP + int1 half-matmul.
// EXACT R12/R14 version (best measured pool).  TMA ring 3x16KB;
// MLP confined to warps 0-3 (4 rows each).
// ============================================================
__global__ void __launch_bounds__(256, 4) pool_mlp_kernel(
    const float* __restrict__ q,  const float* __restrict__ k,
    const float* __restrict__ w1, const float* __restrict__ b1,
    const float* __restrict__ w2, const float* __restrict__ b2,
    const float* __restrict__ w3, const float* __restrict__ b3,
    const float* __restrict__ wi1)
{
    __shared__ __align__(128) float buf[NSTG][CHUNK/4];   // 3 x 16KB
    __shared__ __align__(8)  unsigned long long mbar[NSTG];
    __shared__ float h1s[16][HID];
    __shared__ float h2s[16][HID2];

    int blk = blockIdx.x;            // 0..511
    int t   = blk >> 8;              // 0=q, 1=k
    int bn  = blk & 255;             // b*64 + n
    int tid = threadIdx.x;           // 0..255

    uint32_t mb0 = smem_u32(mbar);
    uint32_t sb0 = smem_u32(buf);

    if (tid == 0) {
        #pragma unroll
        for (int p = 0; p < NSTG; p++)
            asm volatile("mbarrier.init.shared.b64 [%0], 1;"
                         :: "r"(mb0 + p*8) : "memory");
    }
    __syncthreads();

    const char* gsrc = (const char*)((t ? k : q) + (size_t)bn * (128 * 2048));

    if (tid == 0) {
        #pragma unroll
        for (int p = 0; p < NSTG; p++) {
            asm volatile("mbarrier.arrive.expect_tx.shared.b64 _, [%0], %1;"
                         :: "r"(mb0 + p*8), "r"(CHUNK) : "memory");
            asm volatile(
                "cp.async.bulk.shared::cluster.global.mbarrier::complete_tx::bytes "
                "[%0], [%1], %2, [%3];"
                :: "r"(sb0 + p*CHUNK), "l"(gsrc + (size_t)p * CHUNK),
                   "r"(CHUNK), "r"(mb0 + p*8) : "memory");
        }
    }

    float4 a0 = make_float4(0.f,0.f,0.f,0.f);   // column tid
    float4 a1 = make_float4(0.f,0.f,0.f,0.f);   // column tid+256
    int st = 0, ph = 0;
    for (int s = 0; s < 64; s++) {              // 64 chunks x 2 rows
        mbar_wait(mb0 + st*8, ph);
        const float4* sv = (const float4*)buf[st];
        float4 r0a = sv[tid];           // row 2s,   col tid
        float4 r0b = sv[tid + 256];     // row 2s,   col tid+256
        float4 r1a = sv[tid + 512];     // row 2s+1, col tid
        float4 r1b = sv[tid + 768];     // row 2s+1, col tid+256
        a0.x += r0a.x; a0.y += r0a.y; a0.z += r0a.z; a0.w += r0a.w;
        a0.x += r1a.x; a0.y += r1a.y; a0.z += r1a.z; a0.w += r1a.w;
        a1.x += r0b.x; a1.y += r0b.y; a1.z += r0b.z; a1.w += r0b.w;
        a1.x += r1b.x; a1.y += r1b.y; a1.z += r1b.z; a1.w += r1b.w;
        __syncthreads();           // all reads of buf[st] done before reissue
        if (tid == 0 && s + NSTG < 64) {
            asm volatile("mbarrier.arrive.expect_tx.shared.b64 _, [%0], %1;"
                         :: "r"(mb0 + st*8), "r"(CHUNK) : "memory");
            asm volatile(
                "cp.async.bulk.shared::cluster.global.mbarrier::complete_tx::bytes "
                "[%0], [%1], %2, [%3];"
                :: "r"(sb0 + st*CHUNK), "l"(gsrc + (size_t)(s + NSTG) * CHUNK),
                   "r"(CHUNK), "r"(mb0 + st*8) : "memory");
        }
        if (++st == NSTG) { st = 0; ph ^= 1; }
    }

    // pooled means -> xs (overlay ring buffer 0; streaming finished)
    float (*xs)[DD] = (float(*)[DD])buf[0];
    const float r = 1.0f / 128.0f;
    {
        int c0 = tid, c1 = tid + 256;     // column c: h = c>>5, d4 = c&31
        float4 o0 = make_float4(a0.x*r, a0.y*r, a0.z*r, a0.w*r);
        float4 o1 = make_float4(a1.x*r, a1.y*r, a1.z*r, a1.w*r);
        __syncthreads();                  // everyone past last buffer read
        ((float4*)xs[c0 >> 5])[c0 & 31] = o0;
        ((float4*)xs[c1 >> 5])[c1 & 31] = o1;
    }
    __syncthreads();

    // ---- MLP: warps 0-3, each handles 4 rows with shared weight loads ----
    int w    = tid >> 5;
    int lane = tid & 31;
    if (w < 4) {
        int r0 = w * 4;
        float a1v[4], apv[4];
        float b1l = b1[lane];
        #pragma unroll
        for (int i = 0; i < 4; i++) { a1v[i] = b1l; apv[i] = 0.f; }
        const float* wi1t = wi1 + (t ? DD*HID : 0);   // w_int1[:D] / [D:]
        #pragma unroll 4
        for (int d = 0; d < DD; d++) {
            float w1v = w1  [d*HID + lane];
            float wiv = wi1t[d*HID + lane];
            #pragma unroll
            for (int i = 0; i < 4; i++) {
                float xd = xs[r0 + i][d];
                a1v[i] = fmaf(xd, w1v, a1v[i]);
                apv[i] = fmaf(xd, wiv, apv[i]);
            }
        }
        #pragma unroll
        for (int i = 0; i < 4; i++) {
            int row = bn * 16 + r0 + i;
            g_part[t][(size_t)row * HID + lane] = apv[i];
            h1s[r0 + i][lane] = fmaxf(a1v[i], 0.f);
        }
        __syncwarp();
        if (lane < HID2) {
            #pragma unroll
            for (int i = 0; i < 4; i++) {
                float a2 = b2[lane];
                #pragma unroll
                for (int c = 0; c < HID; c++)
                    a2 = fmaf(h1s[r0 + i][c], w2[c*HID2 + lane], a2);
                h2s[r0 + i][lane] = fmaxf(a2, 0.f);
            }
        }
        __syncwarp();
        if (lane < 4) {
            float a3 = b3[0];
            #pragma unroll
            for (int c = 0; c < HID2; c++)
                a3 = fmaf(h2s[r0 + lane][c], w3[c], a3);
            g_imp[t][bn * 16 + r0 + lane] = 1.0f / (1.0f + expf(-a3));
        }
    }
}

// ============================================================
// K2: interaction + combined score.  Now 512 blocks (8-row i-tiles)
// for ~3.5 blocks/SM instead of 1.7 — halves the per-block critical
// path.  Same FP op order; same output positions.
// ============================================================
__global__ void __launch_bounds__(256) inter_kernel(
    const float* __restrict__ bi1,
    const float* __restrict__ wi2,
    const float* __restrict__ bi2)
{
    __shared__ float qp[8*HID];
    __shared__ float kp[64*33];         // padded to 33: conflict-free
    __shared__ float qi[8], ki[64];

    int blk  = blockIdx.x;              // 0..511
    int b    = blk >> 7;
    int rest = blk & 127;
    int h    = rest >> 3;
    int it   = rest & 7;                // i tile (8 rows each)
    int tid  = threadIdx.x;

    // weights are harness inputs (not produced by pool) — safe pre-sync
    float bbv[HID], wwv[HID];
    #pragma unroll
    for (int c = 0; c < HID; c++) { bbv[c] = bi1[c]; wwv[c] = wi2[c]; }
    float bi2v = bi2[0];

    cudaGridDependencySynchronize();    // pool outputs ready after this

    for (int idx = tid; idx < 64*HID; idx += 256) {
        int j = idx >> 5, c = idx & 31;
        kp[j*33 + c] = g_part[1][(((size_t)b*NB + j)*HH + h)*HID + c];
    }
    for (int idx = tid; idx < 8*HID; idx += 256) {
        int il = idx >> 5, c = idx & 31;
        qp[idx] = g_part[0][(((size_t)b*NB + (it*8 + il))*HH + h)*HID + c];
    }
    if (tid < 64)       ki[tid]    = g_imp[1][(b*NB + tid)*HH + h];
    else if (tid < 72)  qi[tid-64] = g_imp[0][(b*NB + it*8 + (tid-64))*HH + h];
    __syncthreads();

    #pragma unroll
    for (int rr = 0; rr < 2; rr++) {
        int p  = tid + 256*rr;          // 0..511 : (il, j)
        int il = p >> 6;
        int j  = p & 63;
        float acc = 0.f;
        #pragma unroll
        for (int c = 0; c < HID; c++)
            acc = fmaf(fmaxf((qp[il*HID + c] + kp[j*33 + c]) + bbv[c], 0.f), wwv[c], acc);
        float inter = 1.0f / (1.0f + expf(-(acc + bi2v)));
        float score = (qi[il] * ki[j]) * inter;
        int i = it*8 + il;
        g_scores[((size_t)b << 16) + (size_t)i*1024 + j*16 + h] = score;
    }
}

// ============================================================
// K3: per-group top-1024 via 4-pass MSB radix select.
// Now 1024 threads / 4 keys per thread (32 warp-private hist
// planes): halves the per-thread key-load / mask-store chains.
// Tie-break by lowest index (thread m-chunks contiguous ascending).
// ============================================================
#define HPITCH 257
__global__ void __launch_bounds__(1024) topk_kernel(float* __restrict__ out) {
    __shared__ unsigned int hist[32 * HPITCH];
    __shared__ unsigned int comb[256];
    __shared__ unsigned int s_prefix;
    __shared__ int s_kk;
    __shared__ int warp_tot[32];

    int g    = blockIdx.x;            // 0..63
    int tid  = threadIdx.x;           // 0..1023
    int lane = tid & 31;
    int wid  = tid >> 5;

    if (tid == 0) { s_prefix = 0u; s_kk = KP; }

    cudaGridDependencySynchronize();  // g_scores ready after this

    const float4* src = (const float4*)(g_scores + (size_t)g * GSIZE) + tid;
    float4 v0 = __ldcs(src);
    unsigned int key[4];
    key[0]=__float_as_uint(v0.x); key[1]=__float_as_uint(v0.y);
    key[2]=__float_as_uint(v0.z); key[3]=__float_as_uint(v0.w);

    unsigned int* myhist = hist + wid * HPITCH;

    #pragma unroll
    for (int pass = 0; pass < 4; pass++) {
        int shift = 24 - pass * 8;
        for (int idx = tid; idx < 32 * HPITCH; idx += 1024) hist[idx] = 0u;
        __syncthreads();
        unsigned int pf = s_prefix;
        #pragma unroll
        for (int m = 0; m < 4; m++) {
            unsigned int kk = key[m];
            bool match = (pass == 0) || ((kk >> (shift + 8)) == pf);
            if (match) atomicAdd(&myhist[(kk >> shift) & 255u], 1u);
        }
        __syncthreads();
        if (tid < 256) {
            unsigned int s = 0u;
            #pragma unroll
            for (int w = 0; w < 32; w++) s += hist[w * HPITCH + tid];
            comb[tid] = s;
        }
        __syncthreads();
        if (wid == 0) {
            unsigned int v[8], tot = 0u;
            #pragma unroll
            for (int m = 0; m < 8; m++) { v[m] = comb[lane*8 + m]; tot += v[m]; }
            unsigned int suf = tot;
            #pragma unroll
            for (int off = 1; off < 32; off <<= 1) {
                unsigned int o = __shfl_down_sync(0xffffffffu, suf, off);
                if (lane + off < 32) suf += o;
            }
            unsigned int above = suf - tot;
            int kcur = s_kk;
            unsigned int cum[8];
            unsigned int run = above;
            #pragma unroll
            for (int m = 7; m >= 0; m--) { run += v[m]; cum[m] = run; }
            #pragma unroll
            for (int m = 0; m < 8; m++) {
                unsigned int cnext = (m < 7) ? cum[m+1] : above;
                if ((int)cum[m] >= kcur && (int)cnext < kcur) {
                    s_prefix = (pf << 8) | (unsigned int)(lane*8 + m);
                    s_kk     = kcur - (int)cnext;
                }
            }
        }
        __syncthreads();
    }

    unsigned int T = s_prefix;    // exact key of the k-th largest
    int need = s_kk;              // number of ==T to keep, lowest index first

    int cnt = 0;
    #pragma unroll
    for (int m = 0; m < 4; m++) cnt += (key[m] == T);
    int x = cnt;
    #pragma unroll
    for (int off = 1; off < 32; off <<= 1) {
        int o = __shfl_up_sync(0xffffffffu, x, off);
        if (lane >= off) x += o;
    }
    if (lane == 31) warp_tot[wid] = x;
    __syncthreads();
    if (tid < 32) {
        int wv = warp_tot[tid];
        #pragma unroll
        for (int off = 1; off < 32; off <<= 1) {
            int o = __shfl_up_sync(0xffffffffu, wv, off);
            if (tid >= off) wv += o;
        }
        warp_tot[tid] = wv;   // inclusive warp prefix
    }
    __syncthreads();
    int rank = (wid > 0 ? warp_tot[wid - 1] : 0) + (x - cnt);

    float sel[4];
    #pragma unroll
    for (int m = 0; m < 4; m++) {
        unsigned int kk = key[m];
        float s = 0.0f;
        if (kk > T) s = 1.0f;
        else if (kk == T) { if (rank < need) s = 1.0f; rank++; }
        sel[m] = s;
    }
    float4* o = (float4*)(out + (size_t)g * GSIZE) + tid;
    o[0] = make_float4(sel[0], sel[1], sel[2], sel[3]);
}

// ============================================================
extern "C" void kernel_launch(void* const* d_in, const int* in_sizes, int n_in,
                              void* d_out, int out_size) {
    const float* q      = (const float*)d_in[0];
    const float* k      = (const float*)d_in[1];
    const float* w_imp1 = (const float*)d_in[2];
    const float* b_imp1 = (const float*)d_in[3];
    const float* w_imp2 = (const float*)d_in[4];
    const float* b_imp2 = (const float*)d_in[5];
    const float* w_imp3 = (const float*)d_in[6];
    const float* b_imp3 = (const float*)d_in[7];
    const float* w_int1 = (const float*)d_in[8];
    const float* b_int1 = (const float*)d_in[9];
    const float* w_int2 = (const float*)d_in[10];
    const float* b_int2 = (const float*)d_in[11];

    pool_mlp_kernel<<<512, 256>>>(q, k, w_imp1, b_imp1, w_imp2, b_imp2,
                                  w_imp3, b_imp3, w_int1);

    // PDL launches: overlap launch + prologue with predecessor
    cudaLaunchAttribute attrs[1];
    attrs[0].id = cudaLaunchAttributeProgrammaticStreamSerialization;
    attrs[0].val.programmaticStreamSerializationAllowed = 1;

    {
        cudaLaunchConfig_t cfg = {};
        cfg.gridDim = dim3(512); cfg.blockDim = dim3(256);
        cfg.attrs = attrs; cfg.numAttrs = 1; cfg.stream = 0;
        cudaLaunchKernelEx(&cfg, inter_kernel, b_int1, w_int2, b_int2);
    }
    {
        cudaLaunchConfig_t cfg = {};
        cfg.gridDim = dim3(NGROUPS); cfg.blockDim = dim3(1024);
        cfg.attrs = attrs; cfg.numAttrs = 1; cfg.stream = 0;
        float* outp = (float*)d_out;
        cudaLaunchKernelEx(&cfg, topk_kernel, outp);
    }
}

// round 16
// speedup vs baseline: 1.0211x; 1.0211x over previous
#include <cuda_runtime.h>
#include <cuda_bf16.h>
#include <math.h>
#include <stdint.h>

// Problem constants (fixed by setup_inputs)
#define BB   4
#define SS   8192
#define HH   16
#define DD   128
#define NB   64      // SS / 128
#define HID  32
#define HID2 16
#define KP   1024    // nb*nb*0.25
#define NGROUPS (BB*HH)   // 64
#define GSIZE   (NB*NB)   // 4096
#define NSTG 3            // TMA pipeline stages
#define CHUNK 16384       // bytes per stage = 2 s-rows

// ---- scratch (device globals; no allocation allowed) ----
__device__ float g_imp [2][BB*NB*HH];      // importance scores
__device__ float g_part[2][BB*NB*HH*HID];  // q_part / k_part
__device__ float g_scores[BB*HH*GSIZE];    // combined, flat-linear order

__device__ __forceinline__ uint32_t smem_u32(const void* p) {
    uint32_t a;
    asm("{ .reg .u64 t; cvta.to.shared.u64 t, %1; cvt.u32.u64 %0, t; }"
        : "=r"(a) : "l"(p));
    return a;
}

__device__ __forceinline__ void mbar_wait(uint32_t mbar, int phase) {
    asm volatile(
        "{\n\t"
        ".reg .pred P;\n\t"
        "W%=:\n\t"
        "mbarrier.try_wait.parity.acquire.cta.shared::cta.b64 P, [%0], %1, 0x989680;\n\t"
        "@P bra D%=;\n\t"
        "bra W%=;\n\t"
        "D%=:\n\t"
        "}"
        :: "r"(mbar), "r"(phase) : "memory");
}

// ============================================================
// K1: fused block-mean pooling + importance MLP + int1 half-matmul.
// Best measured pool (86.9-88.4us @ 76-78.6% DRAM = ~6.2TB/s, the
// path-independent streaming ceiling).  TMA ring 3x16KB; MLP
// confined to warps 0-3 (4 rows each) — 8-warp spread regressed
// twice (R6, R13) and is rejected.
// ============================================================
__global__ void __launch_bounds__(256, 4) pool_mlp_kernel(
    const float* __restrict__ q,  const float* __restrict__ k,
    const float* __restrict__ w1, const float* __restrict__ b1,
    const float* __restrict__ w2, const float* __restrict__ b2,
    const float* __restrict__ w3, const float* __restrict__ b3,
    const float* __restrict__ wi1)
{
    __shared__ __align__(128) float buf[NSTG][CHUNK/4];   // 3 x 16KB
    __shared__ __align__(8)  unsigned long long mbar[NSTG];
    __shared__ float h1s[16][HID];
    __shared__ float h2s[16][HID2];

    int blk = blockIdx.x;            // 0..511
    int t   = blk >> 8;              // 0=q, 1=k
    int bn  = blk & 255;             // b*64 + n
    int tid = threadIdx.x;           // 0..255

    uint32_t mb0 = smem_u32(mbar);
    uint32_t sb0 = smem_u32(buf);

    if (tid == 0) {
        #pragma unroll
        for (int p = 0; p < NSTG; p++)
            asm volatile("mbarrier.init.shared.b64 [%0], 1;"
                         :: "r"(mb0 + p*8) : "memory");
    }
    __syncthreads();

    const char* gsrc = (const char*)((t ? k : q) + (size_t)bn * (128 * 2048));

    if (tid == 0) {
        #pragma unroll
        for (int p = 0; p < NSTG; p++) {
            asm volatile("mbarrier.arrive.expect_tx.shared.b64 _, [%0], %1;"
                         :: "r"(mb0 + p*8), "r"(CHUNK) : "memory");
            asm volatile(
                "cp.async.bulk.shared::cluster.global.mbarrier::complete_tx::bytes "
                "[%0], [%1], %2, [%3];"
                :: "r"(sb0 + p*CHUNK), "l"(gsrc + (size_t)p * CHUNK),
                   "r"(CHUNK), "r"(mb0 + p*8) : "memory");
        }
    }

    float4 a0 = make_float4(0.f,0.f,0.f,0.f);   // column tid
    float4 a1 = make_float4(0.f,0.f,0.f,0.f);   // column tid+256
    int st = 0, ph = 0;
    for (int s = 0; s < 64; s++) {              // 64 chunks x 2 rows
        mbar_wait(mb0 + st*8, ph);
        const float4* sv = (const float4*)buf[st];
        float4 r0a = sv[tid];           // row 2s,   col tid
        float4 r0b = sv[tid + 256];     // row 2s,   col tid+256
        float4 r1a = sv[tid + 512];     // row 2s+1, col tid
        float4 r1b = sv[tid + 768];     // row 2s+1, col tid+256
        a0.x += r0a.x; a0.y += r0a.y; a0.z += r0a.z; a0.w += r0a.w;
        a0.x += r1a.x; a0.y += r1a.y; a0.z += r1a.z; a0.w += r1a.w;
        a1.x += r0b.x; a1.y += r0b.y; a1.z += r0b.z; a1.w += r0b.w;
        a1.x += r1b.x; a1.y += r1b.y; a1.z += r1b.z; a1.w += r1b.w;
        __syncthreads();           // all reads of buf[st] done before reissue
        if (tid == 0 && s + NSTG < 64) {
            asm volatile("mbarrier.arrive.expect_tx.shared.b64 _, [%0], %1;"
                         :: "r"(mb0 + st*8), "r"(CHUNK) : "memory");
            asm volatile(
                "cp.async.bulk.shared::cluster.global.mbarrier::complete_tx::bytes "
                "[%0], [%1], %2, [%3];"
                :: "r"(sb0 + st*CHUNK), "l"(gsrc + (size_t)(s + NSTG) * CHUNK),
                   "r"(CHUNK), "r"(mb0 + st*8) : "memory");
        }
        if (++st == NSTG) { st = 0; ph ^= 1; }
    }

    // pooled means -> xs (overlay ring buffer 0; streaming finished)
    float (*xs)[DD] = (float(*)[DD])buf[0];
    const float r = 1.0f / 128.0f;
    {
        int c0 = tid, c1 = tid + 256;     // column c: h = c>>5, d4 = c&31
        float4 o0 = make_float4(a0.x*r, a0.y*r, a0.z*r, a0.w*r);
        float4 o1 = make_float4(a1.x*r, a1.y*r, a1.z*r, a1.w*r);
        __syncthreads();                  // everyone past last buffer read
        ((float4*)xs[c0 >> 5])[c0 & 31] = o0;
        ((float4*)xs[c1 >> 5])[c1 & 31] = o1;
    }
    __syncthreads();

    // ---- MLP: warps 0-3, each handles 4 rows with shared weight loads ----
    int w    = tid >> 5;
    int lane = tid & 31;
    if (w < 4) {
        int r0 = w * 4;
        float a1v[4], apv[4];
        float b1l = b1[lane];
        #pragma unroll
        for (int i = 0; i < 4; i++) { a1v[i] = b1l; apv[i] = 0.f; }
        const float* wi1t = wi1 + (t ? DD*HID : 0);   // w_int1[:D] / [D:]
        #pragma unroll 4
        for (int d = 0; d < DD; d++) {
            float w1v = w1  [d*HID + lane];
            float wiv = wi1t[d*HID + lane];
            #pragma unroll
            for (int i = 0; i < 4; i++) {
                float xd = xs[r0 + i][d];
                a1v[i] = fmaf(xd, w1v, a1v[i]);
                apv[i] = fmaf(xd, wiv, apv[i]);
            }
        }
        #pragma unroll
        for (int i = 0; i < 4; i++) {
            int row = bn * 16 + r0 + i;
            g_part[t][(size_t)row * HID + lane] = apv[i];
            h1s[r0 + i][lane] = fmaxf(a1v[i], 0.f);
        }
        __syncwarp();
        if (lane < HID2) {
            #pragma unroll
            for (int i = 0; i < 4; i++) {
                float a2 = b2[lane];
                #pragma unroll
                for (int c = 0; c < HID; c++)
                    a2 = fmaf(h1s[r0 + i][c], w2[c*HID2 + lane], a2);
                h2s[r0 + i][lane] = fmaxf(a2, 0.f);
            }
        }
        __syncwarp();
        if (lane < 4) {
            float a3 = b3[0];
            #pragma unroll
            for (int c = 0; c < HID2; c++)
                a3 = fmaf(h2s[r0 + lane][c], w3[c], a3);
            g_imp[t][bn * 16 + r0 + lane] = 1.0f / (1.0f + expf(-a3));
        }
    }
}

// ============================================================
// K2: interaction + combined score (R14 exact: 256 blocks, 16-row
// i-tiles).  PDL: grid-dependency sync before first pool-output load.
// ============================================================
__global__ void __launch_bounds__(256) inter_kernel(
    const float* __restrict__ bi1,
    const float* __restrict__ wi2,
    const float* __restrict__ bi2)
{
    __shared__ float qp[16*HID];
    __shared__ float kp[64*33];         // padded to 33: conflict-free
    __shared__ float qi[16], ki[64];

    int blk  = blockIdx.x;              // 0..255
    int b    = blk >> 6;
    int rest = blk & 63;
    int h    = rest >> 2;
    int it   = rest & 3;                // i tile (16 rows each)
    int tid  = threadIdx.x;

    // weights are harness inputs (not produced by pool) — safe pre-sync
    float bbv[HID], wwv[HID];
    #pragma unroll
    for (int c = 0; c < HID; c++) { bbv[c] = bi1[c]; wwv[c] = wi2[c]; }
    float bi2v = bi2[0];

    cudaGridDependencySynchronize();    // pool outputs ready after this

    for (int idx = tid; idx < 64*HID; idx += 256) {
        int j = idx >> 5, c = idx & 31;
        kp[j*33 + c] = g_part[1][(((size_t)b*NB + j)*HH + h)*HID + c];
    }
    for (int idx = tid; idx < 16*HID; idx += 256) {
        int il = idx >> 5, c = idx & 31;
        qp[idx] = g_part[0][(((size_t)b*NB + (it*16 + il))*HH + h)*HID + c];
    }
    if (tid < 64)       ki[tid]    = g_imp[1][(b*NB + tid)*HH + h];
    else if (tid < 80)  qi[tid-64] = g_imp[0][(b*NB + it*16 + (tid-64))*HH + h];
    __syncthreads();

    #pragma unroll
    for (int rr = 0; rr < 4; rr++) {
        int p  = tid + 256*rr;          // 0..1023 : (il, j)
        int il = p >> 6;
        int j  = p & 63;
        float acc = 0.f;
        #pragma unroll
        for (int c = 0; c < HID; c++)
            acc = fmaf(fmaxf((qp[il*HID + c] + kp[j*33 + c]) + bbv[c], 0.f), wwv[c], acc);
        float inter = 1.0f / (1.0f + expf(-(acc + bi2v)));
        float score = (qi[il] * ki[j]) * inter;
        int i = it*16 + il;
        g_scores[((size_t)b << 16) + (size_t)i*1024 + j*16 + h] = score;
    }
}

// ============================================================
// K3: per-group top-1024 via 4-pass MSB radix select (R14 exact:
// 512 threads, 8 keys/thread, 16 warp-private hist planes).
// PDL: grid-dependency sync before loading g_scores.
// ============================================================
#define HPITCH 257
__global__ void __launch_bounds__(512) topk_kernel(float* __restrict__ out) {
    __shared__ unsigned int hist[16 * HPITCH];
    __shared__ unsigned int comb[256];
    __shared__ unsigned int s_prefix;
    __shared__ int s_kk;
    __shared__ int warp_tot[16];

    int g    = blockIdx.x;            // 0..63
    int tid  = threadIdx.x;           // 0..511
    int lane = tid & 31;
    int wid  = tid >> 5;

    if (tid == 0) { s_prefix = 0u; s_kk = KP; }

    cudaGridDependencySynchronize();  // g_scores ready after this

    const float4* src = (const float4*)(g_scores + (size_t)g * GSIZE) + tid * 2;
    float4 v0 = __ldcs(src);
    float4 v1 = __ldcs(src + 1);
    unsigned int key[8];
    key[0]=__float_as_uint(v0.x); key[1]=__float_as_uint(v0.y);
    key[2]=__float_as_uint(v0.z); key[3]=__float_as_uint(v0.w);
    key[4]=__float_as_uint(v1.x); key[5]=__float_as_uint(v1.y);
    key[6]=__float_as_uint(v1.z); key[7]=__float_as_uint(v1.w);

    unsigned int* myhist = hist + wid * HPITCH;

    #pragma unroll
    for (int pass = 0; pass < 4; pass++) {
        int shift = 24 - pass * 8;
        for (int idx = tid; idx < 16 * HPITCH; idx += 512) hist[idx] = 0u;
        __syncthreads();
        unsigned int pf = s_prefix;
        #pragma unroll
        for (int m = 0; m < 8; m++) {
            unsigned int kk = key[m];
            bool match = (pass == 0) || ((kk >> (shift + 8)) == pf);
            if (match) atomicAdd(&myhist[(kk >> shift) & 255u], 1u);
        }
        __syncthreads();
        if (tid < 256) {
            unsigned int s = 0u;
            #pragma unroll
            for (int w = 0; w < 16; w++) s += hist[w * HPITCH + tid];
            comb[tid] = s;
        }
        __syncthreads();
        if (wid == 0) {
            unsigned int v[8], tot = 0u;
            #pragma unroll
            for (int m = 0; m < 8; m++) { v[m] = comb[lane*8 + m]; tot += v[m]; }
            unsigned int suf = tot;
            #pragma unroll
            for (int off = 1; off < 32; off <<= 1) {
                unsigned int o = __shfl_down_sync(0xffffffffu, suf, off);
                if (lane + off < 32) suf += o;
            }
            unsigned int above = suf - tot;
            int kcur = s_kk;
            unsigned int cum[8];
            unsigned int run = above;
            #pragma unroll
            for (int m = 7; m >= 0; m--) { run += v[m]; cum[m] = run; }
            #pragma unroll
            for (int m = 0; m < 8; m++) {
                unsigned int cnext = (m < 7) ? cum[m+1] : above;
                if ((int)cum[m] >= kcur && (int)cnext < kcur) {
                    s_prefix = (pf << 8) | (unsigned int)(lane*8 + m);
                    s_kk     = kcur - (int)cnext;
                }
            }
        }
        __syncthreads();
    }

    unsigned int T = s_prefix;    // exact key of the k-th largest
    int need = s_kk;              // number of ==T to keep, lowest index first

    int cnt = 0;
    #pragma unroll
    for (int m = 0; m < 8; m++) cnt += (key[m] == T);
    int x = cnt;
    #pragma unroll
    for (int off = 1; off < 32; off <<= 1) {
        int o = __shfl_up_sync(0xffffffffu, x, off);
        if (lane >= off) x += o;
    }
    if (lane == 31) warp_tot[wid] = x;
    __syncthreads();
    if (tid < 16) {
        int wv = warp_tot[tid];
        #pragma unroll
        for (int off = 1; off < 16; off <<= 1) {
            int o = __shfl_up_sync(0x0000ffffu, wv, off);
            if (tid >= off) wv += o;
        }
        warp_tot[tid] = wv;
    }
    __syncthreads();
    int rank = (wid > 0 ? warp_tot[wid - 1] : 0) + (x - cnt);

    float sel[8];
    #pragma unroll
    for (int m = 0; m < 8; m++) {
        unsigned int kk = key[m];
        float s = 0.0f;
        if (kk > T) s = 1.0f;
        else if (kk == T) { if (rank < need) s = 1.0f; rank++; }
        sel[m] = s;
    }
    float4* o = (float4*)(out + (size_t)g * GSIZE) + tid * 2;
    o[0] = make_float4(sel[0], sel[1], sel[2], sel[3]);
    o[1] = make_float4(sel[4], sel[5], sel[6], sel[7]);
}

// ============================================================
extern "C" void kernel_launch(void* const* d_in, const int* in_sizes, int n_in,
                              void* d_out, int out_size) {
    const float* q      = (const float*)d_in[0];
    const float* k      = (const float*)d_in[1];
    const float* w_imp1 = (const float*)d_in[2];
    const float* b_imp1 = (const float*)d_in[3];
    const float* w_imp2 = (const float*)d_in[4];
    const float* b_imp2 = (const float*)d_in[5];
    const float* w_imp3 = (const float*)d_in[6];
    const float* b_imp3 = (const float*)d_in[7];
    const float* w_int1 = (const float*)d_in[8];
    const float* b_int1 = (const float*)d_in[9];
    const float* w_int2 = (const float*)d_in[10];
    const float* b_int2 = (const float*)d_in[11];

    pool_mlp_kernel<<<512, 256>>>(q, k, w_imp1, b_imp1, w_imp2, b_imp2,
                                  w_imp3, b_imp3, w_int1);

    // PDL launches: overlap launch + prologue with predecessor
    cudaLaunchAttribute attrs[1];
    attrs[0].id = cudaLaunchAttributeProgrammaticStreamSerialization;
    attrs[0].val.programmaticStreamSerializationAllowed = 1;

    {
        cudaLaunchConfig_t cfg = {};
        cfg.gridDim = dim3(256); cfg.blockDim = dim3(256);
        cfg.attrs = attrs; cfg.numAttrs = 1; cfg.stream = 0;
        cudaLaunchKernelEx(&cfg, inter_kernel, b_int1, w_int2, b_int2);
    }
    {
        cudaLaunchConfig_t cfg = {};
        cfg.gridDim = dim3(NGROUPS); cfg.blockDim = dim3(512);
        cfg.attrs = attrs; cfg.numAttrs = 1; cfg.stream = 0;
        float* outp = (float*)d_out;
        cudaLaunchKernelEx(&cfg, topk_kernel, outp);
    }
}